// round 11
// baseline (speedup 1.0000x reference)
#include <cuda_runtime.h>
#include <cuda_bf16.h>
#include <math.h>
#include <stdint.h>

#define NH   4
#define NN   4096
#define DIN  256
#define DOUT 128
#define MT   64          // i-rows per CTA -> 256 CTAs, occ 2
#define JT   32          // j-tile for k3
#define RS   80          // smem row stride bytes (40 bf16), bank-conflict-free ldmatrix

// ---------------- device scratch (no allocations allowed) -------------------
__device__ float          g_h[NH * NN * DOUT];       // h fp32 [hd][n][o]  (8MB)
__device__ __nv_bfloat16  g_hThi[NH * DOUT * NN];    // h^T hi [hd][o][n]  (4MB)
__device__ __nv_bfloat16  g_hTlo[NH * DOUT * NN];    // h^T lo             (4MB)
__device__ float4         g_idat[NH * NN];           // (s_i, e^{s_i}, e^{.2 s_i}, 0)
__device__ float4         g_jdat[NH * NN];           // (s_j, e^{s_j}, e^{.2 s_j}, 0)

typedef unsigned long long ull;

__device__ __forceinline__ uint32_t smem_u32(const void* p) {
    uint32_t a;
    asm("{ .reg .u64 t; cvta.to.shared.u64 t, %1; cvt.u32.u64 %0, t; }" : "=r"(a) : "l"(p));
    return a;
}
__device__ __forceinline__ ull pack2(float x, float y) {
    ull r; asm("mov.b64 %0, {%1, %2};" : "=l"(r) : "f"(x), "f"(y)); return r;
}
__device__ __forceinline__ void fma2(ull& d, ull a, ull b) {
    asm("fma.rn.f32x2 %0, %1, %2, %0;" : "+l"(d) : "l"(a), "l"(b));
}
__device__ __forceinline__ float2 unpack2(ull v) {
    float lo, hi; asm("mov.b64 {%0, %1}, %2;" : "=f"(lo), "=f"(hi) : "l"(v));
    float2 r; r.x = lo; r.y = hi; return r;
}
__device__ __forceinline__ void ldsm4(uint32_t* r, uint32_t addr) {
    asm volatile("ldmatrix.sync.aligned.m8n8.x4.shared.b16 {%0,%1,%2,%3}, [%4];"
                 : "=r"(r[0]), "=r"(r[1]), "=r"(r[2]), "=r"(r[3]) : "r"(addr));
}
__device__ __forceinline__ void mma_bf16(float* d, const uint32_t* a, uint32_t b0, uint32_t b1) {
    asm volatile(
        "mma.sync.aligned.m16n8k16.row.col.f32.bf16.bf16.f32 "
        "{%0,%1,%2,%3}, {%4,%5,%6,%7}, {%8,%9}, {%0,%1,%2,%3};"
        : "+f"(d[0]), "+f"(d[1]), "+f"(d[2]), "+f"(d[3])
        : "r"(a[0]), "r"(a[1]), "r"(a[2]), "r"(a[3]), "r"(b0), "r"(b1));
}
__device__ __forceinline__ uint32_t bf16x2_split_hi(float f0, float f1, uint32_t& lo_out) {
    __nv_bfloat16 b0 = __float2bfloat16(f0), b1 = __float2bfloat16(f1);
    uint32_t hp = ((uint32_t)__bfloat16_as_ushort(b1) << 16) | __bfloat16_as_ushort(b0);
    float r0 = f0 - __bfloat162float(b0), r1 = f1 - __bfloat162float(b1);
    __nv_bfloat16 c0 = __float2bfloat16(r0), c1 = __float2bfloat16(r1);
    lo_out = ((uint32_t)__bfloat16_as_ushort(c1) << 16) | __bfloat16_as_ushort(c0);
    return hp;
}

// ---------------------------------------------------------------------------
// K1: h = x @ W   (measured 33us)
// ---------------------------------------------------------------------------
__global__ __launch_bounds__(256) void k1_gemm_h(const float* __restrict__ x,
                                                 const float* __restrict__ W) {
    __shared__ float xsT[32][68];
    __shared__ float ws[32][128];
    const int hd = blockIdx.y;
    const int n0 = blockIdx.x * 64;
    const int tid = threadIdx.x;
    const int tx = tid & 15, ty = tid >> 4;
    const float* Wh = W + (size_t)hd * DIN * DOUT;

    ull acc[4][4];
#pragma unroll
    for (int r = 0; r < 4; r++)
#pragma unroll
        for (int c = 0; c < 4; c++) acc[r][c] = 0ull;

    for (int kk = 0; kk < DIN; kk += 32) {
        __syncthreads();
#pragma unroll
        for (int it = 0; it < 2; it++) {
            int l = tid + it * 256;
            int r = l >> 3, cg = l & 7;
            float4 v = *(const float4*)(x + (size_t)(n0 + r) * DIN + kk + cg * 4);
            xsT[cg * 4 + 0][r] = v.x; xsT[cg * 4 + 1][r] = v.y;
            xsT[cg * 4 + 2][r] = v.z; xsT[cg * 4 + 3][r] = v.w;
        }
#pragma unroll
        for (int it = 0; it < 4; it++) {
            int l = tid + it * 256;
            ((float4*)&ws[0][0])[l] = *(const float4*)(Wh + (size_t)kk * DOUT + l * 4);
        }
        __syncthreads();
#pragma unroll 8
        for (int k = 0; k < 32; k++) {
            float4 av = *(float4*)&xsT[k][ty * 4];
            float4 b0 = *(float4*)&ws[k][tx * 4];
            float4 b1 = *(float4*)&ws[k][64 + tx * 4];
            ull bb0 = pack2(b0.x, b0.y), bb1 = pack2(b0.z, b0.w);
            ull bb2 = pack2(b1.x, b1.y), bb3 = pack2(b1.z, b1.w);
            float ar[4] = {av.x, av.y, av.z, av.w};
#pragma unroll
            for (int r = 0; r < 4; r++) {
                ull arr = pack2(ar[r], ar[r]);
                fma2(acc[r][0], arr, bb0); fma2(acc[r][1], arr, bb1);
                fma2(acc[r][2], arr, bb2); fma2(acc[r][3], arr, bb3);
            }
        }
    }
#pragma unroll
    for (int r = 0; r < 4; r++) {
        float* dst = g_h + ((size_t)hd * NN + n0 + ty * 4 + r) * DOUT;
        float2 p0 = unpack2(acc[r][0]), p1 = unpack2(acc[r][1]);
        float2 p2 = unpack2(acc[r][2]), p3 = unpack2(acc[r][3]);
        *(float4*)(dst + tx * 4)      = make_float4(p0.x, p0.y, p1.x, p1.y);
        *(float4*)(dst + 64 + tx * 4) = make_float4(p2.x, p2.y, p3.x, p3.y);
    }
}

// ---------------------------------------------------------------------------
// K1b: transpose + bf16 hi/lo split:  g_h[hd][n][o] -> g_hThi/lo[hd][o][n]
// ---------------------------------------------------------------------------
__global__ __launch_bounds__(256) void k1b_t() {
    __shared__ float tile[128][129];
    const int hd = blockIdx.y, n0 = blockIdx.x * 128, tid = threadIdx.x;
    {
        int r = tid >> 1, ch = (tid & 1) * 64;
        const float* src = g_h + ((size_t)hd * NN + n0 + r) * DOUT + ch;
#pragma unroll
        for (int u = 0; u < 16; u++) {
            float4 v = *(const float4*)(src + u * 4);
            tile[r][ch + u * 4 + 0] = v.x; tile[r][ch + u * 4 + 1] = v.y;
            tile[r][ch + u * 4 + 2] = v.z; tile[r][ch + u * 4 + 3] = v.w;
        }
    }
    __syncthreads();
    {
        int o = tid >> 1, nh = (tid & 1) * 64;
        size_t obase = ((size_t)(hd * DOUT + o)) * NN + n0 + nh;
#pragma unroll
        for (int u = 0; u < 32; u++) {
            uint32_t lp;
            uint32_t hp = bf16x2_split_hi(tile[nh + 2 * u][o], tile[nh + 2 * u + 1][o], lp);
            *(uint32_t*)((char*)g_hThi + (obase + 2 * u) * 2) = hp;
            *(uint32_t*)((char*)g_hTlo + (obase + 2 * u) * 2) = lp;
        }
    }
}

// ---------------------------------------------------------------------------
// K2: scores + exp factorizations (unchanged)
// ---------------------------------------------------------------------------
__global__ __launch_bounds__(256) void k2_sef(const float* __restrict__ a) {
    const int warp = threadIdx.x >> 5, lane = threadIdx.x & 31;
    const int ridx = blockIdx.x * 8 + warp;
    const int hd = ridx >> 12;
    const float* hrow = g_h + (size_t)ridx * DOUT;
    const float* ah = a + hd * 256;
    float s1 = 0.f, s2 = 0.f;
#pragma unroll
    for (int c = lane; c < DOUT; c += 32) {
        float hv = hrow[c];
        s1 += hv * ah[c];
        s2 += hv * ah[DOUT + c];
    }
#pragma unroll
    for (int o = 16; o > 0; o >>= 1) {
        s1 += __shfl_xor_sync(0xffffffffu, s1, o);
        s2 += __shfl_xor_sync(0xffffffffu, s2, o);
    }
    if (lane == 0) {
        g_idat[ridx] = make_float4(s1, expf(s1), expf(0.2f * s1), 0.f);
        g_jdat[ridx] = make_float4(s2, expf(s2), expf(0.2f * s2), 0.f);
    }
}

// ---------------------------------------------------------------------------
// K3: HMMA (mma.sync bf16, hi/lo split) PV-GEMM with fused masked weights.
//   CTA: 64 i x 128 o x head; grid (64, 4) = 256 CTAs -> occ 2.
//   8 warps: warp w owns i-rows [16*(w&3), +16), n-cols [64*(w>>2), +64).
//   MMA issue order interleaves 4 accumulators (nb-pairs) -> RAW distance 4.
//   smem: [0] zp (1024) | [1024] zi (256)
//         [2048]  stage0: whi 5120 | wlo 5120 | hhi 10240 | hlo 10240 (30720)
//         [32768] stage1: same
// ---------------------------------------------------------------------------
#define K3_SMEM 63488

extern __shared__ char k3s[];
__global__ __launch_bounds__(256, 2) void k3_hmma(const int* __restrict__ A,
                                                  float* __restrict__ out) {
    const int hd = blockIdx.y, i0 = blockIdx.x * MT;
    const int tid = threadIdx.x, wid = tid >> 5, lane = tid & 31;
    const uint32_t sb = smem_u32(k3s);

    // --- w-build identity: row il2 (0..63), 8 j's starting at jq2
    const int il2 = tid >> 2, jq2 = (tid & 3) * 8, ig = i0 + il2;
    const float4 iv = g_idat[hd * NN + ig];
    const float si = iv.x, Ei = iv.y, Fi = iv.z;
    const int* Ar = A + (size_t)ig * NN;
    const float4* jd = g_jdat + hd * NN;
    // --- h-stage identity: row o = il (0..127), half jh
    const int il = tid >> 1, jh = tid & 1;
    const char* hsrc_hi = (const char*)g_hThi + ((size_t)(hd * DOUT + il)) * NN * 2;
    const char* hsrc_lo = (const char*)g_hTlo + ((size_t)(hd * DOUT + il)) * NN * 2;

    // --- compute-phase ldmatrix lane offsets
    const int aoff = ((wid & 3) * 16 + (lane & 15)) * RS + (lane >> 4) * 16;
    const int boff = ((wid >> 2) * 64 + (lane & 7) + ((lane >> 4) & 1) * 8) * RS
                   + ((lane >> 3) & 1) * 16;

    float acc[8][4];
#pragma unroll
    for (int n = 0; n < 8; n++)
#pragma unroll
        for (int c = 0; c < 4; c++) acc[n][c] = 0.f;
    float zacc = 0.f;

    // ---------------- build tile t into stage s ----------------
    auto build = [&](int t) {
        const int s = t & 1;
        const int j0 = t * JT;
        char* wh = k3s + 2048 + s * 30720;
        char* wl = wh + 5120;
        char* hh = wh + 10240;
        char* hl = wh + 20480;
        {
            float z = 0.f;
#pragma unroll
            for (int q = 0; q < 8; q += 2) {
                const int j = j0 + jq2 + q;
                int2 av = *(const int2*)(Ar + j);
                float4 v0 = jd[j], v1 = jd[j + 1];
                float t0 = si + v0.x, t1 = si + v1.x;
                float w0 = (t0 >= 0.f) ? Ei * v0.y : Fi * v0.z;
                float w1 = (t1 >= 0.f) ? Ei * v1.y : Fi * v1.z;
                if (!((av.x > 0) || (j == ig)))     w0 = 0.f;
                if (!((av.y > 0) || (j + 1 == ig))) w1 = 0.f;
                z += w0 + w1;
                uint32_t lp;
                uint32_t hp = bf16x2_split_hi(w0, w1, lp);
                const uint32_t off = (uint32_t)il2 * RS + (jq2 + q) * 2;
                *(uint32_t*)(wh + off) = hp;
                *(uint32_t*)(wl + off) = lp;
            }
            zacc += z;
        }
        {
            const uint32_t doff = (uint32_t)il * RS + jh * 32;
            const size_t sbyte = (size_t)(j0 + jh * 16) * 2;
            *(float4*)(hh + doff)      = *(const float4*)(hsrc_hi + sbyte);
            *(float4*)(hh + doff + 16) = *(const float4*)(hsrc_hi + sbyte + 16);
            *(float4*)(hl + doff)      = *(const float4*)(hsrc_lo + sbyte);
            *(float4*)(hl + doff + 16) = *(const float4*)(hsrc_lo + sbyte + 16);
        }
    };

    // ---------------- compute tile t from stage s (RAW-distance-4 order) ----
    auto compute = [&](int t) {
        const int s = t & 1;
        const uint32_t wbase = sb + 2048 + s * 30720;
        const uint32_t hbase = wbase + 10240;
#pragma unroll
        for (int kk = 0; kk < 2; kk++) {           // two k16 steps
            const uint32_t kb = kk * 32;           // 16 bf16 = 32 bytes
            uint32_t ahi[4], alo[4];
            ldsm4(ahi, wbase + aoff + kb);
            ldsm4(alo, wbase + 5120 + aoff + kb);
#pragma unroll
            for (int g = 0; g < 2; g++) {          // nb-pair group: nb = 2g, 2g+1
                uint32_t b0h[4], b0l[4], b1h[4], b1l[4];
                const uint32_t hb0 = hbase + (2 * g) * 16 * RS + boff + kb;
                const uint32_t hb1 = hbase + (2 * g + 1) * 16 * RS + boff + kb;
                ldsm4(b0h, hb0);
                ldsm4(b1h, hb1);
                ldsm4(b0l, hb0 + 10240);
                ldsm4(b1l, hb1 + 10240);
                float* a0 = acc[4 * g + 0];
                float* a1 = acc[4 * g + 1];
                float* a2 = acc[4 * g + 2];
                float* a3 = acc[4 * g + 3];
                // 12 MMAs, same-accumulator reuse distance = 4
                mma_bf16(a0, ahi, b0h[0], b0h[1]);
                mma_bf16(a1, ahi, b0h[2], b0h[3]);
                mma_bf16(a2, ahi, b1h[0], b1h[1]);
                mma_bf16(a3, ahi, b1h[2], b1h[3]);
                mma_bf16(a0, ahi, b0l[0], b0l[1]);
                mma_bf16(a1, ahi, b0l[2], b0l[3]);
                mma_bf16(a2, ahi, b1l[0], b1l[1]);
                mma_bf16(a3, ahi, b1l[2], b1l[3]);
                mma_bf16(a0, alo, b0h[0], b0h[1]);
                mma_bf16(a1, alo, b0h[2], b0h[3]);
                mma_bf16(a2, alo, b1h[0], b1h[1]);
                mma_bf16(a3, alo, b1h[2], b1h[3]);
            }
        }
    };

    build(0);
    __syncthreads();
    for (int t = 0; t < NN / JT; t++) {
        compute(t);
        if (t + 1 < NN / JT) build(t + 1);
        __syncthreads();
    }

    // ---- Z reduction (4 partials per i-row)
    float* zp = (float*)(k3s);
    float* zi = (float*)(k3s + 1024);
    zp[tid] = zacc;
    __syncthreads();
    if (tid < MT)
        zi[tid] = 1.0f / (zp[4 * tid] + zp[4 * tid + 1] + zp[4 * tid + 2] + zp[4 * tid + 3]);
    __syncthreads();

    // ---- epilogue: normalize + store
    const int r0 = (wid & 3) * 16 + (lane >> 2), r1 = r0 + 8;
    const float s0 = zi[r0], s1 = zi[r1];
    const int ncol = (wid >> 2) * 64 + (lane & 3) * 2;
    float* o0 = out + (size_t)(i0 + r0) * (NH * DOUT) + hd * DOUT + ncol;
    float* o1 = out + (size_t)(i0 + r1) * (NH * DOUT) + hd * DOUT + ncol;
#pragma unroll
    for (int nt = 0; nt < 8; nt++) {
        *(float2*)(o0 + nt * 8) = make_float2(acc[nt][0] * s0, acc[nt][1] * s0);
        *(float2*)(o1 + nt * 8) = make_float2(acc[nt][2] * s1, acc[nt][3] * s1);
    }
}

// ---------------------------------------------------------------------------
extern "C" void kernel_launch(void* const* d_in, const int* in_sizes, int n_in,
                              void* d_out, int out_size) {
    const float* x = (const float*)d_in[0];   // (4096, 256) f32
    const int*   A = (const int*)d_in[1];     // (4096, 4096) i32
    const float* W = (const float*)d_in[2];   // (4, 256, 128) f32
    const float* a = (const float*)d_in[3];   // (4, 256, 1) f32
    float* out = (float*)d_out;               // (4096, 512) f32

    cudaFuncSetAttribute(k3_hmma, cudaFuncAttributeMaxDynamicSharedMemorySize, K3_SMEM);

    k1_gemm_h<<<dim3(NN / 64, NH), 256>>>(x, W);
    k1b_t<<<dim3(NN / 128, NH), 256>>>();
    k2_sef<<<(NH * NN) / 8, 256>>>(a);
    k3_hmma<<<dim3(NN / MT, NH), 256, K3_SMEM>>>(A, out);
}

// round 14
// speedup vs baseline: 1.3516x; 1.3516x over previous
#include <cuda_runtime.h>
#include <cuda_bf16.h>
#include <cuda_fp16.h>
#include <math.h>
#include <stdint.h>

#define NH   4
#define NN   4096
#define DIN  256
#define DOUT 128
#define MT   64          // i-rows per CTA -> 256 CTAs, occ 2
#define JT   32          // j-tile for k3
#define RS   80          // smem row stride bytes, bank-conflict-free ldmatrix

// ---------------- device scratch (no allocations allowed) -------------------
__device__ float   g_h[NH * NN * DOUT];     // h fp32 [hd][n][o]  (8MB)
__device__ half    g_hT[NH * DOUT * NN];    // h^T fp16 [hd][o][n] (4MB)
__device__ float4  g_idat[NH * NN];         // (s_i, e^{s_i}, e^{.2 s_i}, 0)
__device__ float4  g_jdat[NH * NN];         // (s_j, e^{s_j}, e^{.2 s_j}, 0)

typedef unsigned long long ull;

__device__ __forceinline__ uint32_t smem_u32(const void* p) {
    uint32_t a;
    asm("{ .reg .u64 t; cvta.to.shared.u64 t, %1; cvt.u32.u64 %0, t; }" : "=r"(a) : "l"(p));
    return a;
}
__device__ __forceinline__ ull pack2(float x, float y) {
    ull r; asm("mov.b64 %0, {%1, %2};" : "=l"(r) : "f"(x), "f"(y)); return r;
}
__device__ __forceinline__ void fma2(ull& d, ull a, ull b) {
    asm("fma.rn.f32x2 %0, %1, %2, %0;" : "+l"(d) : "l"(a), "l"(b));
}
__device__ __forceinline__ float2 unpack2(ull v) {
    float lo, hi; asm("mov.b64 {%0, %1}, %2;" : "=f"(lo), "=f"(hi) : "l"(v));
    float2 r; r.x = lo; r.y = hi; return r;
}
__device__ __forceinline__ void ldsm4(uint32_t* r, uint32_t addr) {
    asm volatile("ldmatrix.sync.aligned.m8n8.x4.shared.b16 {%0,%1,%2,%3}, [%4];"
                 : "=r"(r[0]), "=r"(r[1]), "=r"(r[2]), "=r"(r[3]) : "r"(addr));
}
__device__ __forceinline__ void mma_f16(float* d, const uint32_t* a, uint32_t b0, uint32_t b1) {
    asm volatile(
        "mma.sync.aligned.m16n8k16.row.col.f32.f16.f16.f32 "
        "{%0,%1,%2,%3}, {%4,%5,%6,%7}, {%8,%9}, {%0,%1,%2,%3};"
        : "+f"(d[0]), "+f"(d[1]), "+f"(d[2]), "+f"(d[3])
        : "r"(a[0]), "r"(a[1]), "r"(a[2]), "r"(a[3]), "r"(b0), "r"(b1));
}

// ---------------------------------------------------------------------------
// K1: h = x @ W   (measured 33us)
// ---------------------------------------------------------------------------
__global__ __launch_bounds__(256) void k1_gemm_h(const float* __restrict__ x,
                                                 const float* __restrict__ W) {
    __shared__ float xsT[32][68];
    __shared__ float ws[32][128];
    const int hd = blockIdx.y;
    const int n0 = blockIdx.x * 64;
    const int tid = threadIdx.x;
    const int tx = tid & 15, ty = tid >> 4;
    const float* Wh = W + (size_t)hd * DIN * DOUT;

    ull acc[4][4];
#pragma unroll
    for (int r = 0; r < 4; r++)
#pragma unroll
        for (int c = 0; c < 4; c++) acc[r][c] = 0ull;

    for (int kk = 0; kk < DIN; kk += 32) {
        __syncthreads();
#pragma unroll
        for (int it = 0; it < 2; it++) {
            int l = tid + it * 256;
            int r = l >> 3, cg = l & 7;
            float4 v = *(const float4*)(x + (size_t)(n0 + r) * DIN + kk + cg * 4);
            xsT[cg * 4 + 0][r] = v.x; xsT[cg * 4 + 1][r] = v.y;
            xsT[cg * 4 + 2][r] = v.z; xsT[cg * 4 + 3][r] = v.w;
        }
#pragma unroll
        for (int it = 0; it < 4; it++) {
            int l = tid + it * 256;
            ((float4*)&ws[0][0])[l] = *(const float4*)(Wh + (size_t)kk * DOUT + l * 4);
        }
        __syncthreads();
#pragma unroll 8
        for (int k = 0; k < 32; k++) {
            float4 av = *(float4*)&xsT[k][ty * 4];
            float4 b0 = *(float4*)&ws[k][tx * 4];
            float4 b1 = *(float4*)&ws[k][64 + tx * 4];
            ull bb0 = pack2(b0.x, b0.y), bb1 = pack2(b0.z, b0.w);
            ull bb2 = pack2(b1.x, b1.y), bb3 = pack2(b1.z, b1.w);
            float ar[4] = {av.x, av.y, av.z, av.w};
#pragma unroll
            for (int r = 0; r < 4; r++) {
                ull arr = pack2(ar[r], ar[r]);
                fma2(acc[r][0], arr, bb0); fma2(acc[r][1], arr, bb1);
                fma2(acc[r][2], arr, bb2); fma2(acc[r][3], arr, bb3);
            }
        }
    }
#pragma unroll
    for (int r = 0; r < 4; r++) {
        float* dst = g_h + ((size_t)hd * NN + n0 + ty * 4 + r) * DOUT;
        float2 p0 = unpack2(acc[r][0]), p1 = unpack2(acc[r][1]);
        float2 p2 = unpack2(acc[r][2]), p3 = unpack2(acc[r][3]);
        *(float4*)(dst + tx * 4)      = make_float4(p0.x, p0.y, p1.x, p1.y);
        *(float4*)(dst + 64 + tx * 4) = make_float4(p2.x, p2.y, p3.x, p3.y);
    }
}

// ---------------------------------------------------------------------------
// K1b: transpose + fp16 convert:  g_h[hd][n][o] -> g_hT[hd][o][n]
// ---------------------------------------------------------------------------
__global__ __launch_bounds__(256) void k1b_t() {
    __shared__ float tile[128][129];
    const int hd = blockIdx.y, n0 = blockIdx.x * 128, tid = threadIdx.x;
    {
        int r = tid >> 1, ch = (tid & 1) * 64;
        const float* src = g_h + ((size_t)hd * NN + n0 + r) * DOUT + ch;
#pragma unroll
        for (int u = 0; u < 16; u++) {
            float4 v = *(const float4*)(src + u * 4);
            tile[r][ch + u * 4 + 0] = v.x; tile[r][ch + u * 4 + 1] = v.y;
            tile[r][ch + u * 4 + 2] = v.z; tile[r][ch + u * 4 + 3] = v.w;
        }
    }
    __syncthreads();
    {
        int o = tid >> 1, nh = (tid & 1) * 64;
        size_t obase = ((size_t)(hd * DOUT + o)) * NN + n0 + nh;
#pragma unroll
        for (int u = 0; u < 32; u++) {
            __half2 hv = __floats2half2_rn(tile[nh + 2 * u][o], tile[nh + 2 * u + 1][o]);
            *(uint32_t*)((char*)g_hT + (obase + 2 * u) * 2) = *(uint32_t*)&hv;
        }
    }
}

// ---------------------------------------------------------------------------
// K2: scores + exp factorizations (unchanged)
// ---------------------------------------------------------------------------
__global__ __launch_bounds__(256) void k2_sef(const float* __restrict__ a) {
    const int warp = threadIdx.x >> 5, lane = threadIdx.x & 31;
    const int ridx = blockIdx.x * 8 + warp;
    const int hd = ridx >> 12;
    const float* hrow = g_h + (size_t)ridx * DOUT;
    const float* ah = a + hd * 256;
    float s1 = 0.f, s2 = 0.f;
#pragma unroll
    for (int c = lane; c < DOUT; c += 32) {
        float hv = hrow[c];
        s1 += hv * ah[c];
        s2 += hv * ah[DOUT + c];
    }
#pragma unroll
    for (int o = 16; o > 0; o >>= 1) {
        s1 += __shfl_xor_sync(0xffffffffu, s1, o);
        s2 += __shfl_xor_sync(0xffffffffu, s2, o);
    }
    if (lane == 0) {
        g_idat[ridx] = make_float4(s1, expf(s1), expf(0.2f * s1), 0.f);
        g_jdat[ridx] = make_float4(s2, expf(s2), expf(0.2f * s2), 0.f);
    }
}

// ---------------------------------------------------------------------------
// K3: single-product fp16 HMMA PV-GEMM with fused masked weights.
//   CTA: 64 i x 128 o x head; grid (64,4) = 256 CTAs -> occ 2.
//   8 warps: warp w owns i-rows [16*(w&3), +16), n-cols [64*(w>>2), +64).
//   smem: [0] zp (1024) | [1024] zi (256)
//         [2048]            stage0: w 5120 | h 10240   (15360)
//         [2048+15360]      stage1: same
// ---------------------------------------------------------------------------
#define K3_SMEM 32768

extern __shared__ char k3s[];
__global__ __launch_bounds__(256, 2) void k3_hmma(const int* __restrict__ A,
                                                  float* __restrict__ out) {
    const int hd = blockIdx.y, i0 = blockIdx.x * MT;
    const int tid = threadIdx.x, wid = tid >> 5, lane = tid & 31;
    const uint32_t sb = smem_u32(k3s);

    // --- w-build identity: row il2 (0..63), 8 j's starting at jq2
    const int il2 = tid >> 2, jq2 = (tid & 3) * 8, ig = i0 + il2;
    const float4 iv = g_idat[hd * NN + ig];
    const float si = iv.x, Ei = iv.y, Fi = iv.z;
    const int* Ar = A + (size_t)ig * NN;
    const float4* jd = g_jdat + hd * NN;
    // --- h-stage identity: row o = il (0..127), half jh
    const int il = tid >> 1, jh = tid & 1;
    const char* hsrc = (const char*)g_hT + ((size_t)(hd * DOUT + il)) * NN * 2;

    // --- compute-phase ldmatrix lane offsets
    const int aoff = ((wid & 3) * 16 + (lane & 15)) * RS + (lane >> 4) * 16;
    const int boff = ((wid >> 2) * 64 + (lane & 7) + ((lane >> 4) & 1) * 8) * RS
                   + ((lane >> 3) & 1) * 16;

    float acc[8][4];
#pragma unroll
    for (int n = 0; n < 8; n++)
#pragma unroll
        for (int c = 0; c < 4; c++) acc[n][c] = 0.f;
    float zacc = 0.f;

    // ---------------- build tile t into stage s ----------------
    auto build = [&](int t) {
        const int s = t & 1;
        const int j0 = t * JT;
        char* wt = k3s + 2048 + s * 15360;
        char* ht = wt + 5120;
        // w tile: thread covers (row il2, 8 j's at jq2); Z from rounded fp16 w
        {
            float z = 0.f;
#pragma unroll
            for (int q = 0; q < 8; q += 2) {
                const int j = j0 + jq2 + q;
                int2 av = *(const int2*)(Ar + j);
                float4 v0 = jd[j], v1 = jd[j + 1];
                float t0 = si + v0.x, t1 = si + v1.x;
                float w0 = (t0 >= 0.f) ? Ei * v0.y : Fi * v0.z;
                float w1 = (t1 >= 0.f) ? Ei * v1.y : Fi * v1.z;
                if (!((av.x > 0) || (j == ig)))     w0 = 0.f;
                if (!((av.y > 0) || (j + 1 == ig))) w1 = 0.f;
                __half2 hw = __floats2half2_rn(w0, w1);
                z += __half2float(__low2half(hw)) + __half2float(__high2half(hw));
                *(uint32_t*)(wt + (uint32_t)il2 * RS + (jq2 + q) * 2) = *(uint32_t*)&hw;
            }
            zacc += z;
        }
        // h tile: thread copies 32B of row il (o), half jh
        {
            const uint32_t doff = (uint32_t)il * RS + jh * 32;
            const size_t sbyte = (size_t)(j0 + jh * 16) * 2;
            *(float4*)(ht + doff)      = *(const float4*)(hsrc + sbyte);
            *(float4*)(ht + doff + 16) = *(const float4*)(hsrc + sbyte + 16);
        }
    };

    // ---------------- compute tile t from stage s ----------------
    auto compute = [&](int t) {
        const uint32_t wbase = sb + 2048 + (t & 1) * 15360;
        const uint32_t hbase = wbase + 5120;
#pragma unroll
        for (int kk = 0; kk < 2; kk++) {           // two k16 steps
            const uint32_t kb = kk * 32;           // 16 fp16 = 32 bytes
            uint32_t a[4];
            ldsm4(a, wbase + aoff + kb);
#pragma unroll
            for (int nb = 0; nb < 4; nb++) {
                uint32_t b[4];
                ldsm4(b, hbase + nb * 16 * RS + boff + kb);
                mma_f16(acc[2 * nb],     a, b[0], b[1]);
                mma_f16(acc[2 * nb + 1], a, b[2], b[3]);
            }
        }
    };

    build(0);
    __syncthreads();
    for (int t = 0; t < NN / JT; t++) {
        compute(t);
        if (t + 1 < NN / JT) build(t + 1);
        __syncthreads();
    }

    // ---- Z reduction (4 partials per i-row)
    float* zp = (float*)(k3s);
    float* zi = (float*)(k3s + 1024);
    zp[tid] = zacc;
    __syncthreads();
    if (tid < MT)
        zi[tid] = 1.0f / (zp[4 * tid] + zp[4 * tid + 1] + zp[4 * tid + 2] + zp[4 * tid + 3]);
    __syncthreads();

    // ---- epilogue: normalize + store
    const int r0 = (wid & 3) * 16 + (lane >> 2), r1 = r0 + 8;
    const float s0 = zi[r0], s1 = zi[r1];
    const int ncol = (wid >> 2) * 64 + (lane & 3) * 2;
    float* o0 = out + (size_t)(i0 + r0) * (NH * DOUT) + hd * DOUT + ncol;
    float* o1 = out + (size_t)(i0 + r1) * (NH * DOUT) + hd * DOUT + ncol;
#pragma unroll
    for (int nt = 0; nt < 8; nt++) {
        *(float2*)(o0 + nt * 8) = make_float2(acc[nt][0] * s0, acc[nt][1] * s0);
        *(float2*)(o1 + nt * 8) = make_float2(acc[nt][2] * s1, acc[nt][3] * s1);
    }
}

// ---------------------------------------------------------------------------
extern "C" void kernel_launch(void* const* d_in, const int* in_sizes, int n_in,
                              void* d_out, int out_size) {
    const float* x = (const float*)d_in[0];   // (4096, 256) f32
    const int*   A = (const int*)d_in[1];     // (4096, 4096) i32
    const float* W = (const float*)d_in[2];   // (4, 256, 128) f32
    const float* a = (const float*)d_in[3];   // (4, 256, 1) f32
    float* out = (float*)d_out;               // (4096, 512) f32

    cudaFuncSetAttribute(k3_hmma, cudaFuncAttributeMaxDynamicSharedMemorySize, K3_SMEM);

    k1_gemm_h<<<dim3(NN / 64, NH), 256>>>(x, W);
    k1b_t<<<dim3(NN / 128, NH), 256>>>();
    k2_sef<<<(NH * NN) / 8, 256>>>(a);
    k3_hmma<<<dim3(NN / MT, NH), 256, K3_SMEM>>>(A, out);
}

// round 15
// speedup vs baseline: 1.5091x; 1.1166x over previous
#include <cuda_runtime.h>
#include <cuda_bf16.h>
#include <cuda_fp16.h>
#include <math.h>
#include <stdint.h>

#define NH   4
#define NN   4096
#define DIN  256
#define DOUT 128
#define MT   64          // i-rows per CTA -> 256 CTAs, occ 2
#define JT   32          // j-tile for k3
#define RS   80          // smem row stride bytes, bank-conflict-free ldmatrix

// ---------------- device scratch (no allocations allowed) -------------------
__device__ float   g_h[NH * NN * DOUT];      // h fp32 [hd][n][o]  (8MB)
__device__ half    g_hT2[NH * 128 * DOUT * 32]; // h^T fp16 [hd][jtile][o][32] (4MB)
__device__ float4  g_idat[NH * NN];          // (s_i, e^{s_i}, e^{.2 s_i}, 0)
__device__ float4  g_jdat[NH * NN];          // (s_j, e^{s_j}, e^{.2 s_j}, 0)

typedef unsigned long long ull;

__device__ __forceinline__ uint32_t smem_u32(const void* p) {
    uint32_t a;
    asm("{ .reg .u64 t; cvta.to.shared.u64 t, %1; cvt.u32.u64 %0, t; }" : "=r"(a) : "l"(p));
    return a;
}
__device__ __forceinline__ ull pack2(float x, float y) {
    ull r; asm("mov.b64 %0, {%1, %2};" : "=l"(r) : "f"(x), "f"(y)); return r;
}
__device__ __forceinline__ void fma2(ull& d, ull a, ull b) {
    asm("fma.rn.f32x2 %0, %1, %2, %0;" : "+l"(d) : "l"(a), "l"(b));
}
__device__ __forceinline__ float2 unpack2(ull v) {
    float lo, hi; asm("mov.b64 {%0, %1}, %2;" : "=f"(lo), "=f"(hi) : "l"(v));
    float2 r; r.x = lo; r.y = hi; return r;
}
__device__ __forceinline__ void ldsm4(uint32_t* r, uint32_t addr) {
    asm volatile("ldmatrix.sync.aligned.m8n8.x4.shared.b16 {%0,%1,%2,%3}, [%4];"
                 : "=r"(r[0]), "=r"(r[1]), "=r"(r[2]), "=r"(r[3]) : "r"(addr));
}
__device__ __forceinline__ void mma_f16(float* d, const uint32_t* a, uint32_t b0, uint32_t b1) {
    asm volatile(
        "mma.sync.aligned.m16n8k16.row.col.f32.f16.f16.f32 "
        "{%0,%1,%2,%3}, {%4,%5,%6,%7}, {%8,%9}, {%0,%1,%2,%3};"
        : "+f"(d[0]), "+f"(d[1]), "+f"(d[2]), "+f"(d[3])
        : "r"(a[0]), "r"(a[1]), "r"(a[2]), "r"(a[3]), "r"(b0), "r"(b1));
}

// ---------------------------------------------------------------------------
// K1: h = x @ W   (measured 33us)
// ---------------------------------------------------------------------------
__global__ __launch_bounds__(256) void k1_gemm_h(const float* __restrict__ x,
                                                 const float* __restrict__ W) {
    __shared__ float xsT[32][68];
    __shared__ float ws[32][128];
    const int hd = blockIdx.y;
    const int n0 = blockIdx.x * 64;
    const int tid = threadIdx.x;
    const int tx = tid & 15, ty = tid >> 4;
    const float* Wh = W + (size_t)hd * DIN * DOUT;

    ull acc[4][4];
#pragma unroll
    for (int r = 0; r < 4; r++)
#pragma unroll
        for (int c = 0; c < 4; c++) acc[r][c] = 0ull;

    for (int kk = 0; kk < DIN; kk += 32) {
        __syncthreads();
#pragma unroll
        for (int it = 0; it < 2; it++) {
            int l = tid + it * 256;
            int r = l >> 3, cg = l & 7;
            float4 v = *(const float4*)(x + (size_t)(n0 + r) * DIN + kk + cg * 4);
            xsT[cg * 4 + 0][r] = v.x; xsT[cg * 4 + 1][r] = v.y;
            xsT[cg * 4 + 2][r] = v.z; xsT[cg * 4 + 3][r] = v.w;
        }
#pragma unroll
        for (int it = 0; it < 4; it++) {
            int l = tid + it * 256;
            ((float4*)&ws[0][0])[l] = *(const float4*)(Wh + (size_t)kk * DOUT + l * 4);
        }
        __syncthreads();
#pragma unroll 8
        for (int k = 0; k < 32; k++) {
            float4 av = *(float4*)&xsT[k][ty * 4];
            float4 b0 = *(float4*)&ws[k][tx * 4];
            float4 b1 = *(float4*)&ws[k][64 + tx * 4];
            ull bb0 = pack2(b0.x, b0.y), bb1 = pack2(b0.z, b0.w);
            ull bb2 = pack2(b1.x, b1.y), bb3 = pack2(b1.z, b1.w);
            float ar[4] = {av.x, av.y, av.z, av.w};
#pragma unroll
            for (int r = 0; r < 4; r++) {
                ull arr = pack2(ar[r], ar[r]);
                fma2(acc[r][0], arr, bb0); fma2(acc[r][1], arr, bb1);
                fma2(acc[r][2], arr, bb2); fma2(acc[r][3], arr, bb3);
            }
        }
    }
#pragma unroll
    for (int r = 0; r < 4; r++) {
        float* dst = g_h + ((size_t)hd * NN + n0 + ty * 4 + r) * DOUT;
        float2 p0 = unpack2(acc[r][0]), p1 = unpack2(acc[r][1]);
        float2 p2 = unpack2(acc[r][2]), p3 = unpack2(acc[r][3]);
        *(float4*)(dst + tx * 4)      = make_float4(p0.x, p0.y, p1.x, p1.y);
        *(float4*)(dst + 64 + tx * 4) = make_float4(p2.x, p2.y, p3.x, p3.y);
    }
}

// ---------------------------------------------------------------------------
// K1b: transpose + fp16, tile-contiguous layout:
//   g_h[hd][n][o] -> g_hT2[hd][n>>5][o][n&31]
// ---------------------------------------------------------------------------
__global__ __launch_bounds__(256) void k1b_t() {
    __shared__ float tile[128][129];
    const int hd = blockIdx.y, n0 = blockIdx.x * 128, tid = threadIdx.x;
    {
        int r = tid >> 1, ch = (tid & 1) * 64;
        const float* src = g_h + ((size_t)hd * NN + n0 + r) * DOUT + ch;
#pragma unroll
        for (int u = 0; u < 16; u++) {
            float4 v = *(const float4*)(src + u * 4);
            tile[r][ch + u * 4 + 0] = v.x; tile[r][ch + u * 4 + 1] = v.y;
            tile[r][ch + u * 4 + 2] = v.z; tile[r][ch + u * 4 + 3] = v.w;
        }
    }
    __syncthreads();
    {
        int o = tid >> 1, nh = (tid & 1) * 64;
        // tile-contiguous dest: byte addr = ((hd*128 + tile)*128 + o)*64 + jj*2
        size_t tbase = ((size_t)(hd * 128 + ((n0 + nh) >> 5)) * 128 + o) * 64;
#pragma unroll
        for (int u = 0; u < 32; u++) {
            __half2 hv = __floats2half2_rn(tile[nh + 2 * u][o], tile[nh + 2 * u + 1][o]);
            int tt = u >> 4;              // second 32-j tile after u=16
            int jj = (2 * u) & 31;
            *(uint32_t*)((char*)g_hT2 + tbase + (size_t)tt * 8192 + jj * 2) = *(uint32_t*)&hv;
        }
    }
}

// ---------------------------------------------------------------------------
// K2: scores + exp factorizations (unchanged)
// ---------------------------------------------------------------------------
__global__ __launch_bounds__(256) void k2_sef(const float* __restrict__ a) {
    const int warp = threadIdx.x >> 5, lane = threadIdx.x & 31;
    const int ridx = blockIdx.x * 8 + warp;
    const int hd = ridx >> 12;
    const float* hrow = g_h + (size_t)ridx * DOUT;
    const float* ah = a + hd * 256;
    float s1 = 0.f, s2 = 0.f;
#pragma unroll
    for (int c = lane; c < DOUT; c += 32) {
        float hv = hrow[c];
        s1 += hv * ah[c];
        s2 += hv * ah[DOUT + c];
    }
#pragma unroll
    for (int o = 16; o > 0; o >>= 1) {
        s1 += __shfl_xor_sync(0xffffffffu, s1, o);
        s2 += __shfl_xor_sync(0xffffffffu, s2, o);
    }
    if (lane == 0) {
        g_idat[ridx] = make_float4(s1, expf(s1), expf(0.2f * s1), 0.f);
        g_jdat[ridx] = make_float4(s2, expf(s2), expf(0.2f * s2), 0.f);
    }
}

// ---------------------------------------------------------------------------
// K3: single-product fp16 HMMA PV-GEMM, wavefront-optimized build/staging.
//   CTA: 64 i x 128 o x head; grid (64,4) = 256 CTAs -> occ 2.
//   Build: warp w owns w-tile rows [8w, 8w+8); lane l owns column j0+l.
//          jd loaded once per tile per warp; A coalesced LDG.32 per row;
//          row scalars via shfl; per-row Z partials in registers.
//   Compute: warp w computes i-rows [16*(w&3),+16) x n-cols [64*(w>>2),+64).
//   smem: [0] zfull 64f | [1024] zi 64f
//         [2048] stage0: w 5120 | h 10240  | [17408] stage1: same
// ---------------------------------------------------------------------------
#define K3_SMEM 32768

extern __shared__ char k3s[];
__global__ __launch_bounds__(256, 2) void k3_hmma(const int* __restrict__ A,
                                                  float* __restrict__ out) {
    const int hd = blockIdx.y, i0 = blockIdx.x * MT;
    const int tid = threadIdx.x, wid = tid >> 5, lane = tid & 31;
    const uint32_t sb = smem_u32(k3s);

    // --- build identity: warp rows [8*wid, +8), lane column j0+lane
    const int w8 = wid * 8;
    const float4 miv = g_idat[hd * NN + i0 + w8 + (lane & 7)]; // rows' scalars in lanes 0..7
    const float4* jd = g_jdat + hd * NN;
    // --- h-stage identity: row o = il (0..127), half jh (tile-contiguous src)
    const int il = tid >> 1, jh = tid & 1;
    const char* hbase_g = (const char*)g_hT2 + (size_t)hd * 128 * 8192;

    // --- compute-phase ldmatrix lane offsets
    const int aoff = ((wid & 3) * 16 + (lane & 15)) * RS + (lane >> 4) * 16;
    const int boff = ((wid >> 2) * 64 + (lane & 7) + ((lane >> 4) & 1) * 8) * RS
                   + ((lane >> 3) & 1) * 16;

    float acc[8][4];
#pragma unroll
    for (int n = 0; n < 8; n++)
#pragma unroll
        for (int c = 0; c < 4; c++) acc[n][c] = 0.f;
    float zr[8];
#pragma unroll
    for (int r = 0; r < 8; r++) zr[r] = 0.f;

    // ---------------- build tile t into stage s ----------------
    auto build = [&](int t) {
        const int s = t & 1;
        const int j0 = t * JT;
        char* wt = k3s + 2048 + s * 15360;
        char* ht = wt + 5120;
        // w tile rows [w8, w8+8), lane column j = j0+lane
        {
            const int j = j0 + lane;
            const float4 jv = jd[j];
#pragma unroll
            for (int r = 0; r < 8; r++) {
                const int row = w8 + r;
                const float si = __shfl_sync(0xffffffffu, miv.x, r);
                const float Ei = __shfl_sync(0xffffffffu, miv.y, r);
                const float Fi = __shfl_sync(0xffffffffu, miv.z, r);
                const int av = A[(size_t)(i0 + row) * NN + j];
                const float tv = si + jv.x;
                float w = (tv >= 0.f) ? Ei * jv.y : Fi * jv.z;
                if (!((av > 0) || (j == i0 + row))) w = 0.f;
                const half hw = __float2half_rn(w);
                zr[r] += __half2float(hw);
                *(half*)(wt + (uint32_t)row * RS + lane * 2) = hw;
            }
        }
        // h tile: thread copies 32B of row il, half jh (coalesced src)
        {
            const char* src = hbase_g + (size_t)t * 8192 + il * 64 + jh * 32;
            const uint32_t doff = (uint32_t)il * RS + jh * 32;
            *(float4*)(ht + doff)      = *(const float4*)(src);
            *(float4*)(ht + doff + 16) = *(const float4*)(src + 16);
        }
    };

    // ---------------- compute tile t from stage s ----------------
    auto compute = [&](int t) {
        const uint32_t wbase = sb + 2048 + (t & 1) * 15360;
        const uint32_t hbase = wbase + 5120;
#pragma unroll
        for (int kk = 0; kk < 2; kk++) {           // two k16 steps
            const uint32_t kb = kk * 32;           // 16 fp16 = 32 bytes
            uint32_t a[4];
            ldsm4(a, wbase + aoff + kb);
#pragma unroll
            for (int nb = 0; nb < 4; nb++) {
                uint32_t b[4];
                ldsm4(b, hbase + nb * 16 * RS + boff + kb);
                mma_f16(acc[2 * nb],     a, b[0], b[1]);
                mma_f16(acc[2 * nb + 1], a, b[2], b[3]);
            }
        }
    };

    build(0);
    __syncthreads();
    for (int t = 0; t < NN / JT; t++) {
        compute(t);
        if (t + 1 < NN / JT) build(t + 1);
        __syncthreads();
    }

    // ---- Z reduction: warp-reduce each row partial, lane 0 writes
    float* zfull = (float*)(k3s);
    float* zi = (float*)(k3s + 1024);
#pragma unroll
    for (int r = 0; r < 8; r++) {
        float z = zr[r];
#pragma unroll
        for (int o = 16; o > 0; o >>= 1) z += __shfl_xor_sync(0xffffffffu, z, o);
        if (lane == 0) zfull[w8 + r] = z;
    }
    __syncthreads();
    if (tid < MT) zi[tid] = 1.0f / zfull[tid];
    __syncthreads();

    // ---- epilogue: normalize + store
    const int r0 = (wid & 3) * 16 + (lane >> 2), r1 = r0 + 8;
    const float s0 = zi[r0], s1 = zi[r1];
    const int ncol = (wid >> 2) * 64 + (lane & 3) * 2;
    float* o0 = out + (size_t)(i0 + r0) * (NH * DOUT) + hd * DOUT + ncol;
    float* o1 = out + (size_t)(i0 + r1) * (NH * DOUT) + hd * DOUT + ncol;
#pragma unroll
    for (int nt = 0; nt < 8; nt++) {
        *(float2*)(o0 + nt * 8) = make_float2(acc[nt][0] * s0, acc[nt][1] * s0);
        *(float2*)(o1 + nt * 8) = make_float2(acc[nt][2] * s1, acc[nt][3] * s1);
    }
}

// ---------------------------------------------------------------------------
extern "C" void kernel_launch(void* const* d_in, const int* in_sizes, int n_in,
                              void* d_out, int out_size) {
    const float* x = (const float*)d_in[0];   // (4096, 256) f32
    const int*   A = (const int*)d_in[1];     // (4096, 4096) i32
    const float* W = (const float*)d_in[2];   // (4, 256, 128) f32
    const float* a = (const float*)d_in[3];   // (4, 256, 1) f32
    float* out = (float*)d_out;               // (4096, 512) f32

    cudaFuncSetAttribute(k3_hmma, cudaFuncAttributeMaxDynamicSharedMemorySize, K3_SMEM);

    k1_gemm_h<<<dim3(NN / 64, NH), 256>>>(x, W);
    k1b_t<<<dim3(NN / 128, NH), 256>>>();
    k2_sef<<<(NH * NN) / 8, 256>>>(a);
    k3_hmma<<<dim3(NN / MT, NH), 256, K3_SMEM>>>(A, out);
}

// round 17
// speedup vs baseline: 2.3831x; 1.5791x over previous
#include <cuda_runtime.h>
#include <cuda_bf16.h>
#include <cuda_fp16.h>
#include <math.h>
#include <stdint.h>

#define NH   4
#define NN   4096
#define DIN  256
#define DOUT 128
#define MT   64          // i-rows per CTA -> 256 CTAs, occ 2
#define JT   64          // j-tile for k3
#define RS   144         // smem row stride bytes (128B data + 16B pad)

// ---------------- device scratch (no allocations allowed) -------------------
__device__ float   g_h[NH * NN * DOUT];        // h fp32 [hd][n][o]  (8MB)
__device__ half    g_hT3[NH * 64 * DOUT * 64]; // h^T fp16 [hd][jtile64][o][64] (4MB)
__device__ float4  g_idat[NH * NN];            // (s_i, e^{s_i}, e^{.2 s_i}, 0)
__device__ float4  g_jdat[NH * NN];            // (s_j, e^{s_j}, e^{.2 s_j}, 0)

typedef unsigned long long ull;

__device__ __forceinline__ uint32_t smem_u32(const void* p) {
    uint32_t a;
    asm("{ .reg .u64 t; cvta.to.shared.u64 t, %1; cvt.u32.u64 %0, t; }" : "=r"(a) : "l"(p));
    return a;
}
__device__ __forceinline__ ull pack2(float x, float y) {
    ull r; asm("mov.b64 %0, {%1, %2};" : "=l"(r) : "f"(x), "f"(y)); return r;
}
__device__ __forceinline__ void fma2(ull& d, ull a, ull b) {
    asm("fma.rn.f32x2 %0, %1, %2, %0;" : "+l"(d) : "l"(a), "l"(b));
}
__device__ __forceinline__ float2 unpack2(ull v) {
    float lo, hi; asm("mov.b64 {%0, %1}, %2;" : "=f"(lo), "=f"(hi) : "l"(v));
    float2 r; r.x = lo; r.y = hi; return r;
}
__device__ __forceinline__ void ldsm4(uint32_t* r, uint32_t addr) {
    asm volatile("ldmatrix.sync.aligned.m8n8.x4.shared.b16 {%0,%1,%2,%3}, [%4];"
                 : "=r"(r[0]), "=r"(r[1]), "=r"(r[2]), "=r"(r[3]) : "r"(addr));
}
__device__ __forceinline__ void mma_f16(float* d, const uint32_t* a, uint32_t b0, uint32_t b1) {
    asm volatile(
        "mma.sync.aligned.m16n8k16.row.col.f32.f16.f16.f32 "
        "{%0,%1,%2,%3}, {%4,%5,%6,%7}, {%8,%9}, {%0,%1,%2,%3};"
        : "+f"(d[0]), "+f"(d[1]), "+f"(d[2]), "+f"(d[3])
        : "r"(a[0]), "r"(a[1]), "r"(a[2]), "r"(a[3]), "r"(b0), "r"(b1));
}
#define CP_ASYNC16(dst, src) \
    asm volatile("cp.async.ca.shared.global [%0], [%1], 16;" :: "r"(dst), "l"(src) : "memory")
#define CP_COMMIT()  asm volatile("cp.async.commit_group;" ::: "memory")
#define CP_WAIT0()   asm volatile("cp.async.wait_group 0;" ::: "memory")

// ---------------------------------------------------------------------------
// K1: h = x @ W   (measured 33us)
// ---------------------------------------------------------------------------
__global__ __launch_bounds__(256) void k1_gemm_h(const float* __restrict__ x,
                                                 const float* __restrict__ W) {
    __shared__ float xsT[32][68];
    __shared__ float ws[32][128];
    const int hd = blockIdx.y;
    const int n0 = blockIdx.x * 64;
    const int tid = threadIdx.x;
    const int tx = tid & 15, ty = tid >> 4;
    const float* Wh = W + (size_t)hd * DIN * DOUT;

    ull acc[4][4];
#pragma unroll
    for (int r = 0; r < 4; r++)
#pragma unroll
        for (int c = 0; c < 4; c++) acc[r][c] = 0ull;

    for (int kk = 0; kk < DIN; kk += 32) {
        __syncthreads();
#pragma unroll
        for (int it = 0; it < 2; it++) {
            int l = tid + it * 256;
            int r = l >> 3, cg = l & 7;
            float4 v = *(const float4*)(x + (size_t)(n0 + r) * DIN + kk + cg * 4);
            xsT[cg * 4 + 0][r] = v.x; xsT[cg * 4 + 1][r] = v.y;
            xsT[cg * 4 + 2][r] = v.z; xsT[cg * 4 + 3][r] = v.w;
        }
#pragma unroll
        for (int it = 0; it < 4; it++) {
            int l = tid + it * 256;
            ((float4*)&ws[0][0])[l] = *(const float4*)(Wh + (size_t)kk * DOUT + l * 4);
        }
        __syncthreads();
#pragma unroll 8
        for (int k = 0; k < 32; k++) {
            float4 av = *(float4*)&xsT[k][ty * 4];
            float4 b0 = *(float4*)&ws[k][tx * 4];
            float4 b1 = *(float4*)&ws[k][64 + tx * 4];
            ull bb0 = pack2(b0.x, b0.y), bb1 = pack2(b0.z, b0.w);
            ull bb2 = pack2(b1.x, b1.y), bb3 = pack2(b1.z, b1.w);
            float ar[4] = {av.x, av.y, av.z, av.w};
#pragma unroll
            for (int r = 0; r < 4; r++) {
                ull arr = pack2(ar[r], ar[r]);
                fma2(acc[r][0], arr, bb0); fma2(acc[r][1], arr, bb1);
                fma2(acc[r][2], arr, bb2); fma2(acc[r][3], arr, bb3);
            }
        }
    }
#pragma unroll
    for (int r = 0; r < 4; r++) {
        float* dst = g_h + ((size_t)hd * NN + n0 + ty * 4 + r) * DOUT;
        float2 p0 = unpack2(acc[r][0]), p1 = unpack2(acc[r][1]);
        float2 p2 = unpack2(acc[r][2]), p3 = unpack2(acc[r][3]);
        *(float4*)(dst + tx * 4)      = make_float4(p0.x, p0.y, p1.x, p1.y);
        *(float4*)(dst + 64 + tx * 4) = make_float4(p2.x, p2.y, p3.x, p3.y);
    }
}

// ---------------------------------------------------------------------------
// K1b: transpose + fp16, 64-j tile-contiguous layout:
//   g_h[hd][n][o] -> g_hT3[hd][n>>6][o][n&63]
// ---------------------------------------------------------------------------
__global__ __launch_bounds__(256) void k1b_t() {
    __shared__ float tile[128][129];
    const int hd = blockIdx.y, n0 = blockIdx.x * 128, tid = threadIdx.x;
    {
        int r = tid >> 1, ch = (tid & 1) * 64;
        const float* src = g_h + ((size_t)hd * NN + n0 + r) * DOUT + ch;
#pragma unroll
        for (int u = 0; u < 16; u++) {
            float4 v = *(const float4*)(src + u * 4);
            tile[r][ch + u * 4 + 0] = v.x; tile[r][ch + u * 4 + 1] = v.y;
            tile[r][ch + u * 4 + 2] = v.z; tile[r][ch + u * 4 + 3] = v.w;
        }
    }
    __syncthreads();
    {
        int o = tid >> 1, nh = (tid & 1) * 64;   // nh selects which 64-j tile
        size_t tbase = ((size_t)(hd * 64 + ((n0 + nh) >> 6)) * 128 + o) * 128;
#pragma unroll
        for (int u = 0; u < 32; u++) {
            __half2 hv = __floats2half2_rn(tile[nh + 2 * u][o], tile[nh + 2 * u + 1][o]);
            *(uint32_t*)((char*)g_hT3 + tbase + u * 4) = *(uint32_t*)&hv;
        }
    }
}

// ---------------------------------------------------------------------------
// K2: scores + exp factorizations (unchanged)
// ---------------------------------------------------------------------------
__global__ __launch_bounds__(256) void k2_sef(const float* __restrict__ a) {
    const int warp = threadIdx.x >> 5, lane = threadIdx.x & 31;
    const int ridx = blockIdx.x * 8 + warp;
    const int hd = ridx >> 12;
    const float* hrow = g_h + (size_t)ridx * DOUT;
    const float* ah = a + hd * 256;
    float s1 = 0.f, s2 = 0.f;
#pragma unroll
    for (int c = lane; c < DOUT; c += 32) {
        float hv = hrow[c];
        s1 += hv * ah[c];
        s2 += hv * ah[DOUT + c];
    }
#pragma unroll
    for (int o = 16; o > 0; o >>= 1) {
        s1 += __shfl_xor_sync(0xffffffffu, s1, o);
        s2 += __shfl_xor_sync(0xffffffffu, s2, o);
    }
    if (lane == 0) {
        g_idat[ridx] = make_float4(s1, expf(s1), expf(0.2f * s1), 0.f);
        g_jdat[ridx] = make_float4(s2, expf(s2), expf(0.2f * s2), 0.f);
    }
}

// ---------------------------------------------------------------------------
// K3: fp16 HMMA PV-GEMM; JT=64 tiles, cp.async staging, no hot-loop shuffles.
//   CTA: 64 i x 128 o x head; grid (64,4) = 256 CTAs -> occ 2.
//   Build: warp w owns w-rows [8w,+8); lane covers cols j0+lane, j0+32+lane.
//   Compute: warp w computes i-rows [16*(w&3),+16) x n-cols [64*(w>>2),+64).
//   smem: [0] zfull 64f | [1024] zi 64f
//         [2048] stage0: w 64x144=9216 | h 128x144=18432   (27648)
//         [29696] stage1: same                              -> 57344 total
// ---------------------------------------------------------------------------
#define K3_SMEM 57344

extern __shared__ char k3s[];
__global__ __launch_bounds__(256, 2) void k3_hmma(const int* __restrict__ A,
                                                  float* __restrict__ out) {
    const int hd = blockIdx.y, i0 = blockIdx.x * MT;
    const int tid = threadIdx.x, wid = tid >> 5, lane = tid & 31;
    const uint32_t sb = smem_u32(k3s);

    const int w8 = wid * 8;
    const float4* jd = g_jdat + hd * NN;
    const float4* ip = g_idat + hd * NN + i0 + w8;
    // h-stage identity: row o = il (0..127), half jh
    const int il = tid >> 1, jh = tid & 1;
    const char* hbase_g = (const char*)g_hT3 + (size_t)hd * 64 * 16384;

    // compute-phase ldmatrix lane offsets
    const int aoff = ((wid & 3) * 16 + (lane & 15)) * RS + (lane >> 4) * 16;
    const int boff = ((wid >> 2) * 64 + (lane & 7) + ((lane >> 4) & 1) * 8) * RS
                   + ((lane >> 3) & 1) * 16;

    float acc[8][4];
#pragma unroll
    for (int n = 0; n < 8; n++)
#pragma unroll
        for (int c = 0; c < 4; c++) acc[n][c] = 0.f;
    float zr[8];
#pragma unroll
    for (int r = 0; r < 8; r++) zr[r] = 0.f;

    // ---------------- build tile t into stage s ----------------
    auto build = [&](int t) {
        const int s = t & 1;
        const int j0 = t * JT;
        char* wt = k3s + 2048 + s * 27648;
        // h stage via cp.async (tile-contiguous source, fully coalesced)
        {
            const char* src = hbase_g + (size_t)t * 16384 + il * 128 + jh * 64;
            uint32_t dst = sb + 2048 + s * 27648 + 9216 + (uint32_t)il * RS + jh * 64;
            CP_ASYNC16(dst,      src);
            CP_ASYNC16(dst + 16, src + 16);
            CP_ASYNC16(dst + 32, src + 32);
            CP_ASYNC16(dst + 48, src + 48);
        }
        // w tile: rows [w8,+8); lane covers columns j0+lane, j0+32+lane
        const float4 jv0 = jd[j0 + lane];
        const float4 jv1 = jd[j0 + 32 + lane];
        const int* Ap = A + (size_t)(i0 + w8) * NN + j0 + lane;
#pragma unroll
        for (int r = 0; r < 8; r++) {
            const float4 riv = __ldg(ip + r);
            const int a0 = Ap[(size_t)r * NN];
            const int a1 = Ap[(size_t)r * NN + 32];
            const int row = w8 + r;
            float w0 = (riv.x + jv0.x >= 0.f) ? riv.y * jv0.y : riv.z * jv0.z;
            float w1 = (riv.x + jv1.x >= 0.f) ? riv.y * jv1.y : riv.z * jv1.z;
            if (!((a0 > 0) || (j0 + lane == i0 + row)))      w0 = 0.f;
            if (!((a1 > 0) || (j0 + 32 + lane == i0 + row))) w1 = 0.f;
            const half h0 = __float2half_rn(w0), h1 = __float2half_rn(w1);
            zr[r] += __half2float(h0) + __half2float(h1);
            *(half*)(wt + (uint32_t)row * RS + lane * 2)      = h0;
            *(half*)(wt + (uint32_t)row * RS + 64 + lane * 2) = h1;
        }
    };

    // ---------------- compute tile t from stage s ----------------
    auto compute = [&](int t) {
        const uint32_t wb = sb + 2048 + (t & 1) * 27648;
        const uint32_t hb = wb + 9216;
#pragma unroll
        for (int kk = 0; kk < 4; kk++) {           // four k16 steps
            const uint32_t kb = kk * 32;
            uint32_t a[4];
            ldsm4(a, wb + aoff + kb);
#pragma unroll
            for (int nb = 0; nb < 4; nb++) {
                uint32_t b[4];
                ldsm4(b, hb + nb * 16 * RS + boff + kb);
                mma_f16(acc[2 * nb],     a, b[0], b[1]);
                mma_f16(acc[2 * nb + 1], a, b[2], b[3]);
            }
        }
    };

    build(0);
    CP_COMMIT();
    CP_WAIT0();
    __syncthreads();
    for (int t = 0; t < NN / JT; t++) {
        if (t + 1 < NN / JT) { build(t + 1); CP_COMMIT(); }
        compute(t);
        CP_WAIT0();
        __syncthreads();
    }

    // ---- Z reduction: warp-reduce each row partial, lane 0 writes
    float* zfull = (float*)(k3s);
    float* zi = (float*)(k3s + 1024);
#pragma unroll
    for (int r = 0; r < 8; r++) {
        float z = zr[r];
#pragma unroll
        for (int o = 16; o > 0; o >>= 1) z += __shfl_xor_sync(0xffffffffu, z, o);
        if (lane == 0) zfull[w8 + r] = z;
    }
    __syncthreads();
    if (tid < MT) zi[tid] = 1.0f / zfull[tid];
    __syncthreads();

    // ---- epilogue: normalize + store
    const int r0 = (wid & 3) * 16 + (lane >> 2), r1 = r0 + 8;
    const float s0 = zi[r0], s1 = zi[r1];
    const int ncol = (wid >> 2) * 64 + (lane & 3) * 2;
    float* o0 = out + (size_t)(i0 + r0) * (NH * DOUT) + hd * DOUT + ncol;
    float* o1 = out + (size_t)(i0 + r1) * (NH * DOUT) + hd * DOUT + ncol;
#pragma unroll
    for (int nt = 0; nt < 8; nt++) {
        *(float2*)(o0 + nt * 8) = make_float2(acc[nt][0] * s0, acc[nt][1] * s0);
        *(float2*)(o1 + nt * 8) = make_float2(acc[nt][2] * s1, acc[nt][3] * s1);
    }
}

// ---------------------------------------------------------------------------
extern "C" void kernel_launch(void* const* d_in, const int* in_sizes, int n_in,
                              void* d_out, int out_size) {
    const float* x = (const float*)d_in[0];   // (4096, 256) f32
    const int*   A = (const int*)d_in[1];     // (4096, 4096) i32
    const float* W = (const float*)d_in[2];   // (4, 256, 128) f32
    const float* a = (const float*)d_in[3];   // (4, 256, 1) f32
    float* out = (float*)d_out;               // (4096, 512) f32

    cudaFuncSetAttribute(k3_hmma, cudaFuncAttributeMaxDynamicSharedMemorySize, K3_SMEM);

    k1_gemm_h<<<dim3(NN / 64, NH), 256>>>(x, W);
    k1b_t<<<dim3(NN / 128, NH), 256>>>();
    k2_sef<<<(NH * NN) / 8, 256>>>(a);
    k3_hmma<<<dim3(NN / MT, NH), 256, K3_SMEM>>>(A, out);
}